// round 3
// baseline (speedup 1.0000x reference)
#include <cuda_runtime.h>
#include <cuda_bf16.h>

// Problem constants (fixed by the reference)
#define IN_N  (512 * 512)   // input pixels per batch
#define NB    64            // batch
#define NO    (512 * 512)   // outputs
#define NK    8             // connections per output

// Scratch: input transposed to (N, B) so each gather index maps to a
// contiguous 256B run of all 64 batch values. 16.7M floats = 67 MB.
__device__ __align__(256) float g_xT[(size_t)IN_N * NB];

// ---------------------------------------------------------------------------
// Kernel 1: transpose (B, N) -> (N, B).
// Block handles a tile of 64 n-values x 64 batches through padded smem.
// Both the global load and global store are 128B-coalesced; smem accesses
// are conflict-free (pitch 65).
// ---------------------------------------------------------------------------
__global__ void __launch_bounds__(256) transpose_kernel(const float* __restrict__ in) {
    __shared__ float tile[64][65];
    const int n0 = blockIdx.x * 64;
    const int t  = threadIdx.x;

#pragma unroll
    for (int i = 0; i < 16; i++) {
        int e  = t + i * 256;
        int b  = e >> 6;          // 0..63
        int nl = e & 63;          // 0..63
        tile[b][nl] = in[(size_t)b * IN_N + n0 + nl];   // coalesced along n
    }
    __syncthreads();
#pragma unroll
    for (int i = 0; i < 16; i++) {
        int e  = t + i * 256;
        int nl = e >> 6;
        int b  = e & 63;
        // coalesced along b; smem read stride 65 -> conflict-free
        g_xT[(size_t)(n0 + nl) * NB + b] = tile[b][nl];
    }
}

// ---------------------------------------------------------------------------
// Kernel 2: gather + weighted reduce.
// Block = 256 threads = 8 warps; block covers 32 consecutive outputs
// (4 outputs per warp). Lane l owns batches {2l, 2l+1} as a float2.
//
// Per warp:
//   - one 128B coalesced load of conn rows [o..o+3] (32 ints), one for weights
//   - per (output j, k): broadcast idx/w via shfl, then a single fully
//     coalesced 256B warp gather from xT (float2 per lane)
// Results staged in smem (pitch 65) so the final (B, O) writes are
// 128B-coalesced.
// ---------------------------------------------------------------------------
__global__ void __launch_bounds__(256) sparse_linear_kernel(
    const int*   __restrict__ conn,
    const float* __restrict__ w,
    float*       __restrict__ out)
{
    __shared__ float so[32][65];

    const int warp   = threadIdx.x >> 5;
    const int lane   = threadIdx.x & 31;
    const int o_base = blockIdx.x * 32;          // block's 32 outputs
    const int o_warp = o_base + warp * 4;        // this warp's 4 outputs

    // Coalesced load of this warp's 4 conn/weight rows (4 rows x 8 = 32 elems)
    const int   ci = conn[(size_t)o_warp * NK + lane];
    const float wi = w   [(size_t)o_warp * NK + lane];

    const float2* __restrict__ xT2 = reinterpret_cast<const float2*>(g_xT);

    float2 acc[4];
#pragma unroll
    for (int j = 0; j < 4; j++) { acc[j].x = 0.f; acc[j].y = 0.f; }

#pragma unroll
    for (int j = 0; j < 4; j++) {
#pragma unroll
        for (int k = 0; k < NK; k++) {
            int   idx = __shfl_sync(0xffffffffu, ci, j * NK + k);
            float wk  = __shfl_sync(0xffffffffu, wi, j * NK + k);
            // 256B fully-coalesced gather: all 64 batch values for idx
            float2 v = xT2[(size_t)idx * 32 + lane];
            acc[j].x = fmaf(wk, v.x, acc[j].x);
            acc[j].y = fmaf(wk, v.y, acc[j].y);
        }
    }

    // Stage into smem: so[o_local][b]
#pragma unroll
    for (int j = 0; j < 4; j++) {
        so[warp * 4 + j][2 * lane]     = acc[j].x;
        so[warp * 4 + j][2 * lane + 1] = acc[j].y;
    }
    __syncthreads();

    // Coalesced write-out: thread t handles column c = t&31, rows b = t>>5 + 8*i
    const int c  = threadIdx.x & 31;
    const int br = threadIdx.x >> 5;
#pragma unroll
    for (int i = 0; i < 8; i++) {
        int b = br + i * 8;
        // smem read stride 65 across lanes -> conflict-free; 128B global store
        out[(size_t)b * NO + o_base + c] = so[c][b];
    }
}

extern "C" void kernel_launch(void* const* d_in, const int* in_sizes, int n_in,
                              void* d_out, int out_size) {
    const float* input = (const float*)d_in[0];   // (64, 512, 512) f32
    const int*   conn  = (const int*)  d_in[1];   // (O, 8) i32
    const float* wts   = (const float*)d_in[2];   // (O, 8) f32
    float*       out   = (float*)d_out;           // (64, O) f32

    transpose_kernel<<<IN_N / 64, 256>>>(input);
    sparse_linear_kernel<<<NO / 32, 256>>>(conn, wts, out);
}

// round 4
// speedup vs baseline: 1.1440x; 1.1440x over previous
#include <cuda_runtime.h>
#include <cuda_fp16.h>
#include <cuda_bf16.h>

// Problem constants (fixed by the reference)
#define IN_N  (512 * 512)   // input pixels per batch
#define NB    64            // batch
#define NO    (512 * 512)   // outputs
#define NK    8             // connections per output

// Scratch: input transposed to (N, B) in fp16 so each gather index maps to a
// contiguous 128B run of all 64 batch values. 16.7M halves = 33.5 MB
// (L2-resident; halves L1 sector work and L2 gather bytes vs fp32).
__device__ __align__(256) __half g_xTh[(size_t)IN_N * NB];

// ---------------------------------------------------------------------------
// Kernel 1: transpose (B, N) f32 -> (N, B) f16.
// Block handles a 64n x 64b tile via padded smem. Global load is 128B-
// coalesced along n; global store is 128B-coalesced half2 along b.
// ---------------------------------------------------------------------------
__global__ void __launch_bounds__(256) transpose_kernel(const float* __restrict__ in) {
    __shared__ float tile[64][65];
    const int n0 = blockIdx.x * 64;
    const int t  = threadIdx.x;

#pragma unroll
    for (int i = 0; i < 16; i++) {
        int e  = t + i * 256;
        int b  = e >> 6;          // 0..63
        int nl = e & 63;          // 0..63
        tile[b][nl] = in[(size_t)b * IN_N + n0 + nl];   // coalesced along n
    }
    __syncthreads();

    __half2* __restrict__ xTh2 = reinterpret_cast<__half2*>(g_xTh);
#pragma unroll
    for (int i = 0; i < 8; i++) {
        int e  = t + i * 256;        // half2 element id: 64 n x 32 half2
        int nl = e >> 5;             // 0..63
        int bh = e & 31;             // half2 index -> batches {2bh, 2bh+1}
        float lo = tile[2 * bh][nl];     // 2-way smem conflict, DRAM-bound anyway
        float hi = tile[2 * bh + 1][nl];
        xTh2[(size_t)(n0 + nl) * 32 + bh] = __floats2half2_rn(lo, hi);
    }
}

// ---------------------------------------------------------------------------
// Kernel 2: gather + weighted reduce.
// Block = 256 threads = 8 warps; block covers 32 consecutive outputs
// (4 outputs per warp). Lane l owns batches {2l, 2l+1} (one half2 gather,
// fp32 accumulate).
//
// Per warp:
//   - one 128B coalesced load of conn rows [o..o+3] (32 ints), one for weights
//   - per (output j, k): broadcast idx/w via shfl, then a single fully
//     coalesced 128B warp gather from xTh (half2 per lane)
// Results staged in smem (pitch 65) so the final (B, O) writes are
// 128B-coalesced.
// ---------------------------------------------------------------------------
__global__ void __launch_bounds__(256) sparse_linear_kernel(
    const int*   __restrict__ conn,
    const float* __restrict__ w,
    float*       __restrict__ out)
{
    __shared__ float so[32][65];

    const int warp   = threadIdx.x >> 5;
    const int lane   = threadIdx.x & 31;
    const int o_base = blockIdx.x * 32;          // block's 32 outputs
    const int o_warp = o_base + warp * 4;        // this warp's 4 outputs

    // Coalesced load of this warp's 4 conn/weight rows (4 rows x 8 = 32 elems)
    const int   ci = conn[(size_t)o_warp * NK + lane];
    const float wi = w   [(size_t)o_warp * NK + lane];

    const __half2* __restrict__ xTh2 = reinterpret_cast<const __half2*>(g_xTh);

    float2 acc[4];
#pragma unroll
    for (int j = 0; j < 4; j++) { acc[j].x = 0.f; acc[j].y = 0.f; }

#pragma unroll
    for (int j = 0; j < 4; j++) {
#pragma unroll
        for (int k = 0; k < NK; k++) {
            int   idx = __shfl_sync(0xffffffffu, ci, j * NK + k);
            float wk  = __shfl_sync(0xffffffffu, wi, j * NK + k);
            // 128B fully-coalesced gather: all 64 batch values for idx
            float2 v = __half22float2(xTh2[(size_t)idx * 32 + lane]);
            acc[j].x = fmaf(wk, v.x, acc[j].x);
            acc[j].y = fmaf(wk, v.y, acc[j].y);
        }
    }

    // Stage into smem: so[o_local][b]
#pragma unroll
    for (int j = 0; j < 4; j++) {
        so[warp * 4 + j][2 * lane]     = acc[j].x;
        so[warp * 4 + j][2 * lane + 1] = acc[j].y;
    }
    __syncthreads();

    // Coalesced write-out: thread t handles column c = t&31, rows b = t>>5 + 8*i
    const int c  = threadIdx.x & 31;
    const int br = threadIdx.x >> 5;
#pragma unroll
    for (int i = 0; i < 8; i++) {
        int b = br + i * 8;
        // smem read stride 65 across lanes -> conflict-free; 128B global store
        out[(size_t)b * NO + o_base + c] = so[c][b];
    }
}

extern "C" void kernel_launch(void* const* d_in, const int* in_sizes, int n_in,
                              void* d_out, int out_size) {
    const float* input = (const float*)d_in[0];   // (64, 512, 512) f32
    const int*   conn  = (const int*)  d_in[1];   // (O, 8) i32
    const float* wts   = (const float*)d_in[2];   // (O, 8) f32
    float*       out   = (float*)d_out;           // (64, O) f32

    transpose_kernel<<<IN_N / 64, 256>>>(input);
    sparse_linear_kernel<<<NO / 32, 256>>>(conn, wts, out);
}

// round 6
// speedup vs baseline: 1.4112x; 1.2335x over previous
#include <cuda_runtime.h>
#include <cuda_fp16.h>
#include <cuda_bf16.h>

// Problem constants (fixed by the reference)
#define IN_N  (512 * 512)   // input pixels per batch
#define NB    64            // batch
#define NO    (512 * 512)   // outputs
#define NK    8             // connections per output

// Scratch: input transposed to (N, B) in fp16: each index row is a contiguous
// 128B run of all 64 batch values (33.5 MB, L2-resident).
__device__ __align__(256) __half g_xTh[(size_t)IN_N * NB];

// ---------------------------------------------------------------------------
// Kernel 1: transpose (B, N) f32 -> (N, B) f16.
// 64n x 64b tile. float4 global loads (256B/warp-row), uint4 global stores
// (512B/warp, 4 full xTh rows). XOR swizzle at 16B granularity keyed on
// (row>>3) makes BOTH smem phases bank-conflict-free.
// ---------------------------------------------------------------------------
__global__ void __launch_bounds__(256) transpose_kernel(const float* __restrict__ in) {
    __shared__ float tile[64][68];   // pitch 68 floats = 17 x 16B (aligned)
    const int n0 = blockIdx.x * 64;
    const int t  = threadIdx.x;
    const float4* __restrict__ in4 = reinterpret_cast<const float4*>(in);

    // Load: 64 batches x 64 n, float4 per thread (4 iters)
#pragma unroll
    for (int i = 0; i < 4; i++) {
        int e = t + i * 256;          // 0..1023
        int b = e >> 4;               // 0..63  (batch)
        int f = e & 15;               // float4 column within the 64-n row
        float4 v = in4[(size_t)b * (IN_N / 4) + (n0 >> 2) + f];
        int fs = f ^ ((b >> 3) & 7);  // 16B-granular XOR swizzle
        *reinterpret_cast<float4*>(&tile[b][fs * 4]) = v;
    }
    __syncthreads();

    // Store: for each n row (128B of fp16), lane chunk g covers batches 8g..8g+7
    uint4* __restrict__ xT4 = reinterpret_cast<uint4*>(g_xTh);
#pragma unroll
    for (int i = 0; i < 2; i++) {
        int e   = t + i * 256;        // 0..511
        int nl  = e >> 3;             // 0..63 (n within tile)
        int g   = e & 7;              // batch chunk
        int f4  = nl >> 2;
        int sub = nl & 3;
        float fv[8];
#pragma unroll
        for (int jj = 0; jj < 8; jj++) {
            int r  = g * 8 + jj;            // batch row; (r>>3)&7 == g
            int fs = f4 ^ g;                // matching de-swizzle
            fv[jj] = tile[r][fs * 4 + sub]; // conflict-free (proven layout)
        }
        __half2 h0 = __floats2half2_rn(fv[0], fv[1]);
        __half2 h1 = __floats2half2_rn(fv[2], fv[3]);
        __half2 h2 = __floats2half2_rn(fv[4], fv[5]);
        __half2 h3 = __floats2half2_rn(fv[6], fv[7]);
        uint4 o;
        o.x = *reinterpret_cast<unsigned int*>(&h0);
        o.y = *reinterpret_cast<unsigned int*>(&h1);
        o.z = *reinterpret_cast<unsigned int*>(&h2);
        o.w = *reinterpret_cast<unsigned int*>(&h3);
        xT4[(size_t)(n0 + nl) * 8 + g] = o;   // 512B/warp fully coalesced
    }
}

// ---------------------------------------------------------------------------
// Kernel 2: gather + weighted reduce (issue-bound -> minimize warp-instrs).
// Block = 256 threads = 8 warps; block covers 32 outputs (4 per warp).
// Lane layout: j = lane>>3 (which of the warp's 4 outputs),
//              c = lane&7  (which 8-batch chunk). One LDG.128 per warp per k
// gathers 512B covering all 4 output rows. fp32 accumulate (8 per lane).
// ---------------------------------------------------------------------------
__global__ void __launch_bounds__(256) sparse_linear_kernel(
    const int*   __restrict__ conn,
    const float* __restrict__ w,
    float*       __restrict__ out)
{
    __shared__ float so[64][33];     // [batch][o_local], pitch 33

    const int warp   = threadIdx.x >> 5;
    const int lane   = threadIdx.x & 31;
    const int o_base = blockIdx.x * 32;
    const int o_warp = o_base + warp * 4;
    const int j      = lane >> 3;    // output within warp's 4
    const int c      = lane & 7;     // batch chunk (8 batches)

    // Coalesced: warp's 4 conn/weight rows (4 x 8 = 32 elems)
    const int   ci = conn[(size_t)o_warp * NK + lane];
    const float wi = w   [(size_t)o_warp * NK + lane];

    const uint4* __restrict__ xT4 = reinterpret_cast<const uint4*>(g_xTh);

    float acc[8];
#pragma unroll
    for (int r = 0; r < 8; r++) acc[r] = 0.f;

#pragma unroll
    for (int k = 0; k < NK; k++) {
        int src   = (lane & 24) + k;                    // lane j*8 + k
        int   idx = __shfl_sync(0xffffffffu, ci, src);
        float wk  = __shfl_sync(0xffffffffu, wi, src);
        uint4 v = xT4[(size_t)idx * 8 + c];             // 512B/warp: 4 rows
        float2 p0 = __half22float2(*reinterpret_cast<__half2*>(&v.x));
        float2 p1 = __half22float2(*reinterpret_cast<__half2*>(&v.y));
        float2 p2 = __half22float2(*reinterpret_cast<__half2*>(&v.z));
        float2 p3 = __half22float2(*reinterpret_cast<__half2*>(&v.w));
        acc[0] = fmaf(wk, p0.x, acc[0]);
        acc[1] = fmaf(wk, p0.y, acc[1]);
        acc[2] = fmaf(wk, p1.x, acc[2]);
        acc[3] = fmaf(wk, p1.y, acc[3]);
        acc[4] = fmaf(wk, p2.x, acc[4]);
        acc[5] = fmaf(wk, p2.y, acc[5]);
        acc[6] = fmaf(wk, p3.x, acc[6]);
        acc[7] = fmaf(wk, p3.y, acc[7]);
    }

    // Stage: lane owns output (warp*4+j), batches c*8 .. c*8+7
#pragma unroll
    for (int r = 0; r < 8; r++)
        so[c * 8 + r][warp * 4 + j] = acc[r];   // 2-way conflict, cheap
    __syncthreads();

    // Coalesced write-out: lane oc -> output column, 8 batch rows per thread
    const int oc = threadIdx.x & 31;
    const int br = threadIdx.x >> 5;
#pragma unroll
    for (int i = 0; i < 8; i++) {
        int b = br * 8 + i;
        out[(size_t)b * NO + o_base + oc] = so[b][oc];  // conflict-free LDS
    }
}

extern "C" void kernel_launch(void* const* d_in, const int* in_sizes, int n_in,
                              void* d_out, int out_size) {
    const float* input = (const float*)d_in[0];   // (64, 512, 512) f32
    const int*   conn  = (const int*)  d_in[1];   // (O, 8) i32
    const float* wts   = (const float*)d_in[2];   // (O, 8) f32
    float*       out   = (float*)d_out;           // (64, O) f32

    transpose_kernel<<<IN_N / 64, 256>>>(input);
    sparse_linear_kernel<<<NO / 32, 256>>>(conn, wts, out);
}

// round 7
// speedup vs baseline: 1.4775x; 1.0470x over previous
#include <cuda_runtime.h>
#include <cuda_fp16.h>
#include <cuda_bf16.h>

// Problem constants (fixed by the reference)
#define IN_N  (512 * 512)   // input pixels per batch
#define NB    64            // batch
#define NO    (512 * 512)   // outputs
#define NK    8             // connections per output

// Scratch: input transposed to (N, B) in fp16: each index row is a contiguous
// 128B run of all 64 batch values (33.5 MB, L2-resident).
__device__ __align__(256) __half g_xTh[(size_t)IN_N * NB];

// ---------------------------------------------------------------------------
// Kernel 1: transpose (B, N) f32 -> (N, B) f16.  (near DRAM floor, unchanged)
// ---------------------------------------------------------------------------
__global__ void __launch_bounds__(256) transpose_kernel(const float* __restrict__ in) {
    __shared__ float tile[64][68];   // pitch 68 floats = 17 x 16B (aligned)
    const int n0 = blockIdx.x * 64;
    const int t  = threadIdx.x;
    const float4* __restrict__ in4 = reinterpret_cast<const float4*>(in);

#pragma unroll
    for (int i = 0; i < 4; i++) {
        int e = t + i * 256;          // 0..1023
        int b = e >> 4;               // 0..63  (batch)
        int f = e & 15;               // float4 column within the 64-n row
        float4 v = in4[(size_t)b * (IN_N / 4) + (n0 >> 2) + f];
        int fs = f ^ ((b >> 3) & 7);  // 16B-granular XOR swizzle
        *reinterpret_cast<float4*>(&tile[b][fs * 4]) = v;
    }
    __syncthreads();

    uint4* __restrict__ xT4 = reinterpret_cast<uint4*>(g_xTh);
#pragma unroll
    for (int i = 0; i < 2; i++) {
        int e   = t + i * 256;        // 0..511
        int nl  = e >> 3;             // 0..63 (n within tile)
        int g   = e & 7;              // batch chunk
        int f4  = nl >> 2;
        int sub = nl & 3;
        float fv[8];
#pragma unroll
        for (int jj = 0; jj < 8; jj++) {
            int r  = g * 8 + jj;            // batch row; (r>>3)&7 == g
            int fs = f4 ^ g;                // matching de-swizzle
            fv[jj] = tile[r][fs * 4 + sub]; // conflict-free
        }
        __half2 h0 = __floats2half2_rn(fv[0], fv[1]);
        __half2 h1 = __floats2half2_rn(fv[2], fv[3]);
        __half2 h2 = __floats2half2_rn(fv[4], fv[5]);
        __half2 h3 = __floats2half2_rn(fv[6], fv[7]);
        uint4 o;
        o.x = *reinterpret_cast<unsigned int*>(&h0);
        o.y = *reinterpret_cast<unsigned int*>(&h1);
        o.z = *reinterpret_cast<unsigned int*>(&h2);
        o.w = *reinterpret_cast<unsigned int*>(&h3);
        xT4[(size_t)(n0 + nl) * 8 + g] = o;   // 512B/warp fully coalesced
    }
}

// ---------------------------------------------------------------------------
// Kernel 2: gather + weighted reduce with packed HFMA2 accumulation.
// Block = 256 threads = 8 warps; block covers 32 outputs (4 per warp).
// Lane layout: j = lane>>3 (output within warp's 4), c = lane&7 (8-batch
// chunk). One LDG.128 per warp per k covers all 4 output rows (512B).
//
// Accumulation: fp16x2 HFMA2, split into two chains (even/odd k, depth 4),
// merged in fp32 in the epilogue to bound rounding error.
// Loop body per k: 2 SHFL + 1 pack + 1 LDG.128 + 4 HFMA2  (~9 warp-instrs
// vs 19 in the fp32 version).
// ---------------------------------------------------------------------------
__global__ void __launch_bounds__(256) sparse_linear_kernel(
    const int*   __restrict__ conn,
    const float* __restrict__ w,
    float*       __restrict__ out)
{
    __shared__ float so[64][33];     // [batch][o_local], pitch 33

    const int warp   = threadIdx.x >> 5;
    const int lane   = threadIdx.x & 31;
    const int o_base = blockIdx.x * 32;
    const int o_warp = o_base + warp * 4;
    const int j      = lane >> 3;    // output within warp's 4
    const int c      = lane & 7;     // batch chunk (8 batches)

    // Coalesced: warp's 4 conn/weight rows (4 x 8 = 32 elems)
    const int   ci = conn[(size_t)o_warp * NK + lane];
    const float wf = w   [(size_t)o_warp * NK + lane];
    // Pre-quantize this lane's weight to fp16; shfl the bits.
    const int   wib = (int)__half_as_ushort(__float2half_rn(wf));

    const uint4* __restrict__ xT4 = reinterpret_cast<const uint4*>(g_xTh);

    __half2 accE[4], accO[4];        // even-k / odd-k chains
#pragma unroll
    for (int m = 0; m < 4; m++) {
        accE[m] = __half2half2(__ushort_as_half((unsigned short)0));
        accO[m] = accE[m];
    }

#pragma unroll
    for (int k = 0; k < NK; k++) {
        int src   = (lane & 24) + k;                    // lane j*8 + k
        int   idx = __shfl_sync(0xffffffffu, ci,  src);
        int   wb  = __shfl_sync(0xffffffffu, wib, src);
        __half2 wk2 = __half2half2(__ushort_as_half((unsigned short)wb));
        uint4 v = xT4[(size_t)idx * 8 + c];             // 512B/warp: 4 rows
        __half2* acc = (k & 1) ? accO : accE;
        acc[0] = __hfma2(wk2, *reinterpret_cast<__half2*>(&v.x), acc[0]);
        acc[1] = __hfma2(wk2, *reinterpret_cast<__half2*>(&v.y), acc[1]);
        acc[2] = __hfma2(wk2, *reinterpret_cast<__half2*>(&v.z), acc[2]);
        acc[3] = __hfma2(wk2, *reinterpret_cast<__half2*>(&v.w), acc[3]);
    }

    // Epilogue: merge chains in fp32, stage to smem.
#pragma unroll
    for (int m = 0; m < 4; m++) {
        float2 e = __half22float2(accE[m]);
        float2 o = __half22float2(accO[m]);
        so[c * 8 + 2 * m    ][warp * 4 + j] = e.x + o.x;
        so[c * 8 + 2 * m + 1][warp * 4 + j] = e.y + o.y;
    }
    __syncthreads();

    // Coalesced write-out: lane oc -> output column, 8 batch rows per thread
    const int oc = threadIdx.x & 31;
    const int br = threadIdx.x >> 5;
#pragma unroll
    for (int i = 0; i < 8; i++) {
        int b = br * 8 + i;
        out[(size_t)b * NO + o_base + oc] = so[b][oc];  // conflict-free LDS
    }
}

extern "C" void kernel_launch(void* const* d_in, const int* in_sizes, int n_in,
                              void* d_out, int out_size) {
    const float* input = (const float*)d_in[0];   // (64, 512, 512) f32
    const int*   conn  = (const int*)  d_in[1];   // (O, 8) i32
    const float* wts   = (const float*)d_in[2];   // (O, 8) f32
    float*       out   = (float*)d_out;           // (64, O) f32

    transpose_kernel<<<IN_N / 64, 256>>>(input);
    sparse_linear_kernel<<<NO / 32, 256>>>(conn, wts, out);
}

// round 8
// speedup vs baseline: 1.4805x; 1.0020x over previous
#include <cuda_runtime.h>
#include <cuda_fp16.h>
#include <cuda_bf16.h>

// Problem constants (fixed by the reference)
#define IN_N  (512 * 512)   // input pixels per batch
#define NB    64            // batch
#define NO    (512 * 512)   // outputs
#define NK    8             // connections per output

// Scratch: input transposed to (N, B) in fp16: each index row is a contiguous
// 128B run of all 64 batch values (33.5 MB, L2-resident).
__device__ __align__(256) __half g_xTh[(size_t)IN_N * NB];

// ---------------------------------------------------------------------------
// Kernel 1: transpose (B, N) f32 -> (N, B) f16, fp16-in-smem, XOR-swizzled.
//
// Tile: 64 n x 64 b per block. smem element s[row=nl][bh] is the half2
// { x[2bh][n0+row], x[2bh+1][n0+row] }, with the uint column stored at
// swizzled chunk (bh>>2) ^ ((row>>2)&7), sub-chunk bh&3.
//
// Phase 1: lane (q = t&7, bh = t>>3): two coalesced float4 loads (rows 2bh,
//          2bh+1; 8 lanes x 16B = 128B per row-group), 4 F2FP packs,
//          4 conflict-free STS.32 (banks (w^(q&7))*4 + (bh&3), all distinct).
// Phase 2: unit (nl, g): one LDS.128 at chunk g^((nl>>2)&7) (conflict-free
//          per 8-lane phase, 16B aligned) + one STG.128; warp stores 512B
//          fully coalesced to xTh.
// ---------------------------------------------------------------------------
__global__ void __launch_bounds__(256) transpose_kernel(const float* __restrict__ in) {
    __shared__ __align__(16) unsigned int s[64 * 32];   // 8 KB
    const int n0 = blockIdx.x * 64;
    const int t  = threadIdx.x;

    // ---- Phase 1: load fp32, convert, store half2 to swizzled smem ----
#pragma unroll
    for (int i0 = 0; i0 < 2; i0++) {
        const int q  = (t & 7) + 8 * i0;      // n-quad 0..15 (n = n0+4q..+3)
        const int bh = t >> 3;                // batch pair 0..31
        const float4* __restrict__ r0 =
            reinterpret_cast<const float4*>(in + (size_t)(2 * bh) * IN_N);
        const float4* __restrict__ r1 =
            reinterpret_cast<const float4*>(in + (size_t)(2 * bh + 1) * IN_N);
        const float4 a = r0[(n0 >> 2) + q];
        const float4 b = r1[(n0 >> 2) + q];
        const int chunk = bh >> 2;
        const int r2    = bh & 3;
        float av[4] = {a.x, a.y, a.z, a.w};
        float bv[4] = {b.x, b.y, b.z, b.w};
#pragma unroll
        for (int i = 0; i < 4; i++) {
            int row = 4 * q + i;
            int sw  = chunk ^ ((row >> 2) & 7);   // (row>>2)&7 == q&7
            __half2 h = __floats2half2_rn(av[i], bv[i]);
            s[row * 32 + sw * 4 + r2] = *reinterpret_cast<unsigned int*>(&h);
        }
    }
    __syncthreads();

    // ---- Phase 2: LDS.128 + coalesced STG.128 ----
    uint4* __restrict__ xT4 = reinterpret_cast<uint4*>(g_xTh);
#pragma unroll
    for (int i1 = 0; i1 < 2; i1++) {
        int u  = t + 256 * i1;                // 0..511
        int nl = u >> 3;                      // 0..63
        int g  = u & 7;                       // 8-batch chunk
        int sw = g ^ ((nl >> 2) & 7);
        uint4 v = *reinterpret_cast<const uint4*>(&s[nl * 32 + sw * 4]);
        xT4[(size_t)(n0 + nl) * 8 + g] = v;   // 512B/warp fully coalesced
    }
}

// ---------------------------------------------------------------------------
// Kernel 2: gather + weighted reduce with packed HFMA2 accumulation.
// (Unchanged from R6 — measured at ~94% of the LTS byte-throughput cap,
//  DRAM traffic exactly compulsory; bytes are irreducible at fp16.)
// ---------------------------------------------------------------------------
__global__ void __launch_bounds__(256) sparse_linear_kernel(
    const int*   __restrict__ conn,
    const float* __restrict__ w,
    float*       __restrict__ out)
{
    __shared__ float so[64][33];     // [batch][o_local], pitch 33

    const int warp   = threadIdx.x >> 5;
    const int lane   = threadIdx.x & 31;
    const int o_base = blockIdx.x * 32;
    const int o_warp = o_base + warp * 4;
    const int j      = lane >> 3;    // output within warp's 4
    const int c      = lane & 7;     // batch chunk (8 batches)

    // Coalesced: warp's 4 conn/weight rows (4 x 8 = 32 elems)
    const int   ci = conn[(size_t)o_warp * NK + lane];
    const float wf = w   [(size_t)o_warp * NK + lane];
    // Pre-quantize this lane's weight to fp16; shfl the bits.
    const int   wib = (int)__half_as_ushort(__float2half_rn(wf));

    const uint4* __restrict__ xT4 = reinterpret_cast<const uint4*>(g_xTh);

    __half2 accE[4], accO[4];        // even-k / odd-k chains (depth 4 each)
#pragma unroll
    for (int m = 0; m < 4; m++) {
        accE[m] = __half2half2(__ushort_as_half((unsigned short)0));
        accO[m] = accE[m];
    }

#pragma unroll
    for (int k = 0; k < NK; k++) {
        int src   = (lane & 24) + k;                    // lane j*8 + k
        int   idx = __shfl_sync(0xffffffffu, ci,  src);
        int   wb  = __shfl_sync(0xffffffffu, wib, src);
        __half2 wk2 = __half2half2(__ushort_as_half((unsigned short)wb));
        uint4 v = xT4[(size_t)idx * 8 + c];             // 512B/warp: 4 rows
        __half2* acc = (k & 1) ? accO : accE;
        acc[0] = __hfma2(wk2, *reinterpret_cast<__half2*>(&v.x), acc[0]);
        acc[1] = __hfma2(wk2, *reinterpret_cast<__half2*>(&v.y), acc[1]);
        acc[2] = __hfma2(wk2, *reinterpret_cast<__half2*>(&v.z), acc[2]);
        acc[3] = __hfma2(wk2, *reinterpret_cast<__half2*>(&v.w), acc[3]);
    }

    // Epilogue: merge chains in fp32, stage to smem.
#pragma unroll
    for (int m = 0; m < 4; m++) {
        float2 e = __half22float2(accE[m]);
        float2 o = __half22float2(accO[m]);
        so[c * 8 + 2 * m    ][warp * 4 + j] = e.x + o.x;
        so[c * 8 + 2 * m + 1][warp * 4 + j] = e.y + o.y;
    }
    __syncthreads();

    // Coalesced write-out: lane oc -> output column, 8 batch rows per thread
    const int oc = threadIdx.x & 31;
    const int br = threadIdx.x >> 5;
#pragma unroll
    for (int i = 0; i < 8; i++) {
        int b = br * 8 + i;
        out[(size_t)b * NO + o_base + oc] = so[b][oc];  // conflict-free LDS
    }
}

extern "C" void kernel_launch(void* const* d_in, const int* in_sizes, int n_in,
                              void* d_out, int out_size) {
    const float* input = (const float*)d_in[0];   // (64, 512, 512) f32
    const int*   conn  = (const int*)  d_in[1];   // (O, 8) i32
    const float* wts   = (const float*)d_in[2];   // (O, 8) f32
    float*       out   = (float*)d_out;           // (64, O) f32

    transpose_kernel<<<IN_N / 64, 256>>>(input);
    sparse_linear_kernel<<<NO / 32, 256>>>(conn, wts, out);
}